// round 4
// baseline (speedup 1.0000x reference)
#include <cuda_runtime.h>

// Problem constants
#define BB 2
#define SS 2048
#define DD 1024
#define HH 16
#define HD 64
#define BH (BB * HH)        // 32
#define MROWS (BB * SS)     // 4096

// ---------------------------------------------------------------------------
// Device scratch (no runtime allocation allowed)
// ---------------------------------------------------------------------------
__device__ float g_q[BH * SS * HD];                 // 16 MB  [bh][s][d]
__device__ float g_k[BH * SS * HD];                 // 16 MB
__device__ float g_v[BH * SS * HD];                 // 16 MB
__device__ float g_logits[(size_t)BH * SS * SS];    // 512 MB, per-CTA-private spill
__device__ float g_ao[(size_t)MROWS * DD];          // 16 MB  attention out, [B,S,D]

// ---------------------------------------------------------------------------
// QKV projection: C[m,n] = sum_k X[m,k] * Wqkv[n,k]
// M=4096, N=3072, K=1024. 64x64 tile, 256 threads, 4x4 per thread,
// double-buffered smem (k-tile 16) with register prefetch.
// Scatters output into g_q/g_k/g_v in [bh][s][d] layout.
// ---------------------------------------------------------------------------
__global__ __launch_bounds__(256, 2)
void qkv_gemm_kernel(const float* __restrict__ X, const float* __restrict__ W) {
    __shared__ float Xs[2][64][20];
    __shared__ float Ws[2][64][20];

    const int tid = threadIdx.x;
    const int ty = tid >> 4;          // 0..15
    const int tx = tid & 15;          // 0..15
    const int m0 = blockIdx.y << 6;
    const int n0 = blockIdx.x << 6;

    const int lr = tid >> 2;          // 0..63 (row within tile)
    const int lc = (tid & 3) << 2;    // 0,4,8,12 (col quad)

    const float* Xg = X + (size_t)(m0 + lr) * DD + lc;
    const float* Wg = W + (size_t)(n0 + lr) * DD + lc;

    float4 fx = *(const float4*)(Xg);
    float4 fw = *(const float4*)(Wg);
    *(float4*)&Xs[0][lr][lc] = fx;
    *(float4*)&Ws[0][lr][lc] = fw;
    __syncthreads();

    float acc[4][4];
#pragma unroll
    for (int i = 0; i < 4; ++i)
#pragma unroll
        for (int j = 0; j < 4; ++j) acc[i][j] = 0.f;

    const int NKT = DD / 16;  // 64
    for (int kt = 0; kt < NKT; ++kt) {
        const int cur = kt & 1;
        if (kt + 1 < NKT) {
            fx = *(const float4*)(Xg + (kt + 1) * 16);
            fw = *(const float4*)(Wg + (kt + 1) * 16);
        }
#pragma unroll
        for (int kk = 0; kk < 16; kk += 4) {
            float4 A[4], Bv[4];
            A[0] = *(const float4*)&Xs[cur][ty      ][kk];
            A[1] = *(const float4*)&Xs[cur][ty + 16 ][kk];
            A[2] = *(const float4*)&Xs[cur][ty + 32 ][kk];
            A[3] = *(const float4*)&Xs[cur][ty + 48 ][kk];
            Bv[0] = *(const float4*)&Ws[cur][tx      ][kk];
            Bv[1] = *(const float4*)&Ws[cur][tx + 16 ][kk];
            Bv[2] = *(const float4*)&Ws[cur][tx + 32 ][kk];
            Bv[3] = *(const float4*)&Ws[cur][tx + 48 ][kk];
#pragma unroll
            for (int i = 0; i < 4; ++i)
#pragma unroll
                for (int j = 0; j < 4; ++j) {
                    acc[i][j] = fmaf(A[i].x, Bv[j].x, acc[i][j]);
                    acc[i][j] = fmaf(A[i].y, Bv[j].y, acc[i][j]);
                    acc[i][j] = fmaf(A[i].z, Bv[j].z, acc[i][j]);
                    acc[i][j] = fmaf(A[i].w, Bv[j].w, acc[i][j]);
                }
        }
        if (kt + 1 < NKT) {
            *(float4*)&Xs[cur ^ 1][lr][lc] = fx;
            *(float4*)&Ws[cur ^ 1][lr][lc] = fw;
            __syncthreads();
        }
    }

    // Scatter: n0 block covers exactly one (which, h), all d in [0,64)
    const int which = n0 >> 10;              // 0=q, 1=k, 2=v
    const int h = (n0 >> 6) & (HH - 1);
    float* dst = (which == 0) ? g_q : ((which == 1) ? g_k : g_v);
    const int b = m0 >> 11;                  // m0 / S
    const int s_off = m0 & (SS - 1);
    float* dbase = dst + (size_t)(b * HH + h) * SS * HD;
#pragma unroll
    for (int i = 0; i < 4; ++i) {
        const int s = s_off + ty + 16 * i;
#pragma unroll
        for (int j = 0; j < 4; ++j) {
            const int d = tx + 16 * j;
            dbase[(size_t)s * HD + d] = acc[i][j];
        }
    }
}

// ---------------------------------------------------------------------------
// stablemax3 s(x), Eq 38. x <= 0 after max subtraction but handle both.
// ---------------------------------------------------------------------------
__device__ __forceinline__ float stablemax_s(float x) {
    if (x >= 0.f) {
        return 1.f + x * (1.f + 0.5f * x * (1.f + x * (1.f / 3.f)));
    } else {
        return 1.f / (1.f - x * (1.f - 0.5f * x * (1.f - x * (1.f / 3.f))));
    }
}

// ---------------------------------------------------------------------------
// Attention: one CTA per (bh, 64-query block). Two phases:
//  P1: logit tiles (scaled) -> private global spill + running row max
//  P2: re-read logits, s(), row sum, P@V accumulate, normalize, store
// Each thread reads back exactly what it wrote (no fences needed).
// ---------------------------------------------------------------------------
__global__ __launch_bounds__(256, 2)
void attn_kernel() {
    __shared__ float bufA[64][68];   // Q in P1, S-tile in P2
    __shared__ float bufB[64][68];   // K-tile in P1, V-tile in P2

    const int tid = threadIdx.x;
    const int ty = tid >> 4;
    const int tx = tid & 15;
    const int bh = blockIdx.x >> 5;
    const int q0 = (blockIdx.x & 31) << 6;

    const float* Qg = g_q + ((size_t)bh * SS + q0) * HD;
    const float* Kg = g_k + (size_t)bh * SS * HD;
    const float* Vg = g_v + (size_t)bh * SS * HD;
    float* Ls = g_logits + (size_t)blockIdx.x * (64 * SS);

    // Load Q tile [64][64] into bufA (float4, coalesced)
#pragma unroll
    for (int p = 0; p < 4; ++p) {
        const int idx = tid + (p << 8);
        const int r = idx >> 4;
        const int c = (idx & 15) << 2;
        *(float4*)&bufA[r][c] = *(const float4*)(Qg + r * HD + c);
    }

    // Prefetch K tile 0
    float4 pre[4];
#pragma unroll
    for (int p = 0; p < 4; ++p) {
        const int idx = tid + (p << 8);
        const int r = idx >> 4;
        const int c = (idx & 15) << 2;
        pre[p] = *(const float4*)(Kg + r * HD + c);
    }

    float rmax[4] = {-1e30f, -1e30f, -1e30f, -1e30f};
    const int NT = SS / 64;  // 32

    // ----------------- Phase 1: logits + row max -----------------
    for (int ct = 0; ct < NT; ++ct) {
        __syncthreads();                       // prior readers of bufB done
#pragma unroll
        for (int p = 0; p < 4; ++p) {
            const int idx = tid + (p << 8);
            const int r = idx >> 4;
            const int c = (idx & 15) << 2;
            *(float4*)&bufB[r][c] = pre[p];
        }
        __syncthreads();
        if (ct + 1 < NT) {
            const float* Kn = Kg + (size_t)(ct + 1) * 64 * HD;
#pragma unroll
            for (int p = 0; p < 4; ++p) {
                const int idx = tid + (p << 8);
                const int r = idx >> 4;
                const int c = (idx & 15) << 2;
                pre[p] = *(const float4*)(Kn + r * HD + c);
            }
        }

        float acc[4][4];
#pragma unroll
        for (int i = 0; i < 4; ++i)
#pragma unroll
            for (int j = 0; j < 4; ++j) acc[i][j] = 0.f;

#pragma unroll
        for (int kk = 0; kk < 64; kk += 4) {
            float4 A[4], Bv[4];
            A[0] = *(const float4*)&bufA[ty      ][kk];
            A[1] = *(const float4*)&bufA[ty + 16 ][kk];
            A[2] = *(const float4*)&bufA[ty + 32 ][kk];
            A[3] = *(const float4*)&bufA[ty + 48 ][kk];
            Bv[0] = *(const float4*)&bufB[tx      ][kk];
            Bv[1] = *(const float4*)&bufB[tx + 16 ][kk];
            Bv[2] = *(const float4*)&bufB[tx + 32 ][kk];
            Bv[3] = *(const float4*)&bufB[tx + 48 ][kk];
#pragma unroll
            for (int i = 0; i < 4; ++i)
#pragma unroll
                for (int j = 0; j < 4; ++j) {
                    acc[i][j] = fmaf(A[i].x, Bv[j].x, acc[i][j]);
                    acc[i][j] = fmaf(A[i].y, Bv[j].y, acc[i][j]);
                    acc[i][j] = fmaf(A[i].z, Bv[j].z, acc[i][j]);
                    acc[i][j] = fmaf(A[i].w, Bv[j].w, acc[i][j]);
                }
        }

        // scale, spill (coalesced, thread-private layout), row max
#pragma unroll
        for (int i = 0; i < 4; ++i) {
            float4 v;
            v.x = acc[i][0] * 0.125f;
            v.y = acc[i][1] * 0.125f;
            v.z = acc[i][2] * 0.125f;
            v.w = acc[i][3] * 0.125f;
            *(float4*)(Ls + (size_t)ct * 4096 + (size_t)tid * 16 + i * 4) = v;
            float m = fmaxf(fmaxf(v.x, v.y), fmaxf(v.z, v.w));
#pragma unroll
            for (int o = 8; o >= 1; o >>= 1)
                m = fmaxf(m, __shfl_xor_sync(0xffffffffu, m, o));
            rmax[i] = fmaxf(rmax[i], m);
        }
    }

    // ----------------- Phase 2: s(), rowsum, P@V -----------------
    float osum[4][4];
#pragma unroll
    for (int i = 0; i < 4; ++i)
#pragma unroll
        for (int j = 0; j < 4; ++j) osum[i][j] = 0.f;
    float rsum[4] = {0.f, 0.f, 0.f, 0.f};

    // Prefetch V tile 0
#pragma unroll
    for (int p = 0; p < 4; ++p) {
        const int idx = tid + (p << 8);
        const int r = idx >> 4;
        const int c = (idx & 15) << 2;
        pre[p] = *(const float4*)(Vg + r * HD + c);
    }

    for (int ct = 0; ct < NT; ++ct) {
        // re-read own logits (issued early, latency covered by syncs/STS below)
        float4 lr4[4];
#pragma unroll
        for (int i = 0; i < 4; ++i)
            lr4[i] = *(const float4*)(Ls + (size_t)ct * 4096 + (size_t)tid * 16 + i * 4);

        __syncthreads();                       // prior GEMM done reading bufA/bufB
#pragma unroll
        for (int p = 0; p < 4; ++p) {
            const int idx = tid + (p << 8);
            const int r = idx >> 4;
            const int c = (idx & 15) << 2;
            *(float4*)&bufB[r][c] = pre[p];
        }
        if (ct + 1 < NT) {
            const float* Vn = Vg + (size_t)(ct + 1) * 64 * HD;
#pragma unroll
            for (int p = 0; p < 4; ++p) {
                const int idx = tid + (p << 8);
                const int r = idx >> 4;
                const int c = (idx & 15) << 2;
                pre[p] = *(const float4*)(Vn + r * HD + c);
            }
        }

        // s() + rowsum partials + store S tile to bufA
#pragma unroll
        for (int i = 0; i < 4; ++i) {
            const int r = ty + 16 * i;
            const float s0 = stablemax_s(lr4[i].x - rmax[i]);
            const float s1 = stablemax_s(lr4[i].y - rmax[i]);
            const float s2 = stablemax_s(lr4[i].z - rmax[i]);
            const float s3 = stablemax_s(lr4[i].w - rmax[i]);
            rsum[i] += (s0 + s1) + (s2 + s3);
            bufA[r][tx      ] = s0;
            bufA[r][tx + 16 ] = s1;
            bufA[r][tx + 32 ] = s2;
            bufA[r][tx + 48 ] = s3;
        }
        __syncthreads();

        // P @ V: osum[r][d] += sum_t S[r][t] * V[t][d]
#pragma unroll
        for (int t = 0; t < 64; t += 4) {
            float4 Sv[4];
            Sv[0] = *(const float4*)&bufA[ty      ][t];
            Sv[1] = *(const float4*)&bufA[ty + 16 ][t];
            Sv[2] = *(const float4*)&bufA[ty + 32 ][t];
            Sv[3] = *(const float4*)&bufA[ty + 48 ][t];
#pragma unroll
            for (int j = 0; j < 4; ++j) {
                const int d = tx + 16 * j;
                const float vv0 = bufB[t + 0][d];
                const float vv1 = bufB[t + 1][d];
                const float vv2 = bufB[t + 2][d];
                const float vv3 = bufB[t + 3][d];
#pragma unroll
                for (int i = 0; i < 4; ++i) {
                    osum[i][j] = fmaf(Sv[i].x, vv0, osum[i][j]);
                    osum[i][j] = fmaf(Sv[i].y, vv1, osum[i][j]);
                    osum[i][j] = fmaf(Sv[i].z, vv2, osum[i][j]);
                    osum[i][j] = fmaf(Sv[i].w, vv3, osum[i][j]);
                }
            }
        }
    }

    // Full row sums (16-lane butterfly)
#pragma unroll
    for (int i = 0; i < 4; ++i) {
        float r = rsum[i];
#pragma unroll
        for (int o = 8; o >= 1; o >>= 1)
            r += __shfl_xor_sync(0xffffffffu, r, o);
        rsum[i] = r;
    }

    // Normalize, write to [B,S,D] with head-concat layout for the final GEMM
    const int b = bh >> 4;
    const int h = bh & (HH - 1);
    float* Og = g_ao + ((size_t)b * SS + q0) * DD + h * HD;
#pragma unroll
    for (int i = 0; i < 4; ++i) {
        const float inv = 1.0f / rsum[i];
        const int r = ty + 16 * i;
#pragma unroll
        for (int j = 0; j < 4; ++j) {
            Og[(size_t)r * DD + tx + 16 * j] = osum[i][j] * inv;
        }
    }
}

// ---------------------------------------------------------------------------
// Output projection: out[m,n] = sum_k AO[m,k] * Wout[n,k] + bias[n]
// M=4096, N=1024, K=1024. Same GEMM structure as QKV.
// ---------------------------------------------------------------------------
__global__ __launch_bounds__(256, 2)
void proj_kernel(const float* __restrict__ Wo, const float* __restrict__ bias,
                 float* __restrict__ out) {
    __shared__ float Xs[2][64][20];
    __shared__ float Ws[2][64][20];

    const int tid = threadIdx.x;
    const int ty = tid >> 4;
    const int tx = tid & 15;
    const int m0 = blockIdx.y << 6;
    const int n0 = blockIdx.x << 6;

    const int lr = tid >> 2;
    const int lc = (tid & 3) << 2;

    const float* Xg = g_ao + (size_t)(m0 + lr) * DD + lc;
    const float* Wg = Wo + (size_t)(n0 + lr) * DD + lc;

    float4 fx = *(const float4*)(Xg);
    float4 fw = *(const float4*)(Wg);
    *(float4*)&Xs[0][lr][lc] = fx;
    *(float4*)&Ws[0][lr][lc] = fw;
    __syncthreads();

    float acc[4][4];
#pragma unroll
    for (int i = 0; i < 4; ++i)
#pragma unroll
        for (int j = 0; j < 4; ++j) acc[i][j] = 0.f;

    const int NKT = DD / 16;
    for (int kt = 0; kt < NKT; ++kt) {
        const int cur = kt & 1;
        if (kt + 1 < NKT) {
            fx = *(const float4*)(Xg + (kt + 1) * 16);
            fw = *(const float4*)(Wg + (kt + 1) * 16);
        }
#pragma unroll
        for (int kk = 0; kk < 16; kk += 4) {
            float4 A[4], Bv[4];
            A[0] = *(const float4*)&Xs[cur][ty      ][kk];
            A[1] = *(const float4*)&Xs[cur][ty + 16 ][kk];
            A[2] = *(const float4*)&Xs[cur][ty + 32 ][kk];
            A[3] = *(const float4*)&Xs[cur][ty + 48 ][kk];
            Bv[0] = *(const float4*)&Ws[cur][tx      ][kk];
            Bv[1] = *(const float4*)&Ws[cur][tx + 16 ][kk];
            Bv[2] = *(const float4*)&Ws[cur][tx + 32 ][kk];
            Bv[3] = *(const float4*)&Ws[cur][tx + 48 ][kk];
#pragma unroll
            for (int i = 0; i < 4; ++i)
#pragma unroll
                for (int j = 0; j < 4; ++j) {
                    acc[i][j] = fmaf(A[i].x, Bv[j].x, acc[i][j]);
                    acc[i][j] = fmaf(A[i].y, Bv[j].y, acc[i][j]);
                    acc[i][j] = fmaf(A[i].z, Bv[j].z, acc[i][j]);
                    acc[i][j] = fmaf(A[i].w, Bv[j].w, acc[i][j]);
                }
        }
        if (kt + 1 < NKT) {
            *(float4*)&Xs[cur ^ 1][lr][lc] = fx;
            *(float4*)&Ws[cur ^ 1][lr][lc] = fw;
            __syncthreads();
        }
    }

#pragma unroll
    for (int i = 0; i < 4; ++i) {
        const int m = m0 + ty + 16 * i;
#pragma unroll
        for (int j = 0; j < 4; ++j) {
            const int n = n0 + tx + 16 * j;
            out[(size_t)m * DD + n] = acc[i][j] + bias[n];
        }
    }
}

// ---------------------------------------------------------------------------
// Launch
// ---------------------------------------------------------------------------
extern "C" void kernel_launch(void* const* d_in, const int* in_sizes, int n_in,
                              void* d_out, int out_size) {
    (void)in_sizes; (void)n_in; (void)out_size;
    const float* x    = (const float*)d_in[0];
    const float* wqkv = (const float*)d_in[1];
    const float* wout = (const float*)d_in[2];
    const float* bout = (const float*)d_in[3];
    float* out = (float*)d_out;

    qkv_gemm_kernel<<<dim3(3 * DD / 64, MROWS / 64), 256>>>(x, wqkv);
    attn_kernel<<<BH * (SS / 64), 256>>>();
    proj_kernel<<<dim3(DD / 64, MROWS / 64), 256>>>(wout, bout, out);
}